// round 12
// baseline (speedup 1.0000x reference)
#include <cuda_runtime.h>
#include <cstdint>

// Shapes fixed: value [8,4096,1024], last [8,1024], W [1024,1024], b [1024].
#define BB 8
#define TT 4096
#define HH 1024

#define RANGES 64              // T-splits per batch (fused kernel grid.x)
#define TR (TT / RANGES)       // 64 timesteps per block
#define NW 8                   // warps per fused block (256 threads)
#define NITER (TR / NW)        // 8 iterations, 1 row per warp per iter

#define OCH 128                // o-splits for query
#define OSEG (HH / OCH)        // 8

// -------- scratch (__device__ globals; no allocation allowed) --------
// g_q: zero at load; re-zeroed by the fused kernel's combine epilogue each
// run, so the atomicAdd accumulation in k_query starts from 0 every replay.
__device__ __align__(16) float g_q[BB * HH];
__device__ __align__(16) float g_cpart[BB * RANGES * HH]; // 2 MB
__device__ float g_mpart[BB * RANGES];
__device__ float g_spart[BB * RANGES];
__device__ int   g_cnt[BB];   // per-batch ticket counters (reset by combiner)

// ---------------------------------------------------------------------
// Kernel 1: q[b,h] += sum_{o in chunk} W[o,h]*last[b,o], accumulated with
// atomicAdd (coalesced REDG). grid (HH/128, OCH) = 1024 blocks, block 128.
// 8 fully-unrolled W loads per thread; W (4 MB) streamed exactly once.
// ---------------------------------------------------------------------
__global__ void k_query(const float* __restrict__ W,
                        const float* __restrict__ last) {
    __shared__ float ls[BB * OSEG];   // 64 floats
    const int oc = blockIdx.y;
    const int h  = blockIdx.x * 128 + threadIdx.x;

    if (threadIdx.x < BB * OSEG) {
        int b = threadIdx.x / OSEG, o = threadIdx.x % OSEG;
        ls[threadIdx.x] = last[b * HH + oc * OSEG + o];
    }
    __syncthreads();

    float wv[OSEG];
#pragma unroll
    for (int o = 0; o < OSEG; o++)
        wv[o] = W[(size_t)(oc * OSEG + o) * HH + h];

    float acc[BB];
#pragma unroll
    for (int b = 0; b < BB; b++) acc[b] = 0.f;
#pragma unroll
    for (int o = 0; o < OSEG; o++) {
#pragma unroll
        for (int b = 0; b < BB; b++)
            acc[b] = fmaf(wv[o], ls[b * OSEG + o], acc[b]);
    }
#pragma unroll
    for (int b = 0; b < BB; b++)
        atomicAdd(&g_q[b * HH + h], acc[b]);
}

// ---------------------------------------------------------------------
// Kernel 2: fused score + online-softmax + context + last-block combine.
// The untested factorial cell: RPW=1 body (v[8]+cx[32] ≈ 80 regs ->
// 3 CTAs/SM allowed, 24 warps, occ ~37%) COMBINED with RANGES=64
// (512 blocks -> 444 concurrent CTAs actually materialize the 3rd CTA,
// unlike R10's 256-block grid that starved it). smem 21KB*3 = 63KB ok,
// regs 80*768 = 61K < 64K RF.
// Lane l, reg 4j+k maps to h = j*128 + l*4 + k.
// ---------------------------------------------------------------------
__global__ __launch_bounds__(256, 3)
void k_fused(const float* __restrict__ value, float* __restrict__ out) {
    __shared__ float4 q_sm[HH / 4];               // 4 KB
    __shared__ float4 red_c[(NW / 2) * (HH / 4)]; // 16 KB
    __shared__ float red_m[NW], red_s[NW];
    __shared__ float s_wgt[RANGES];
    __shared__ float s_invD;
    __shared__ int   s_ticket;

    const int b = blockIdx.y;
    const int r = blockIdx.x;
    const int tid = threadIdx.x;
    const int w = tid >> 5, l = tid & 31;

    q_sm[tid] = reinterpret_cast<const float4*>(g_q)[b * (HH / 4) + tid];
    __syncthreads();

    float cx[32];
#pragma unroll
    for (int i = 0; i < 32; i++) cx[i] = 0.f;
    float mw = -1e30f, sw = 0.f;

    const float4* vb = reinterpret_cast<const float4*>(value)
                     + ((size_t)b * TT + (size_t)r * TR) * (HH / 4);

#pragma unroll
    for (int it = 0; it < NITER; it++) {
        const float4* p = vb + (size_t)(it * NW + w) * (HH / 4) + l;

        float4 v[8];
#pragma unroll
        for (int j = 0; j < 8; j++) v[j] = p[j * 32];

        // Two accumulator chains halve the dot's serial FMA depth.
        float da = 0.f, db = 0.f;
#pragma unroll
        for (int j = 0; j < 8; j += 2) {
            float4 qa = q_sm[j * 32 + l];
            float4 qb = q_sm[(j + 1) * 32 + l];
            da = fmaf(v[j].x, qa.x, da);   db = fmaf(v[j+1].x, qb.x, db);
            da = fmaf(v[j].y, qa.y, da);   db = fmaf(v[j+1].y, qb.y, db);
            da = fmaf(v[j].z, qa.z, da);   db = fmaf(v[j+1].z, qb.z, db);
            da = fmaf(v[j].w, qa.w, da);   db = fmaf(v[j+1].w, qb.w, db);
        }
        float d = da + db;
#pragma unroll
        for (int off = 16; off; off >>= 1)
            d += __shfl_xor_sync(0xFFFFFFFFu, d, off);

        const float m_new = fmaxf(mw, d);
        const float resc  = __expf(mw - m_new);
        const float ps    = __expf(d - m_new);
        mw = m_new;
        sw = fmaf(sw, resc, ps);
#pragma unroll
        for (int j = 0; j < 8; j++) {
            float t;
            t = cx[4*j+0] * resc; cx[4*j+0] = fmaf(ps, v[j].x, t);
            t = cx[4*j+1] * resc; cx[4*j+1] = fmaf(ps, v[j].y, t);
            t = cx[4*j+2] * resc; cx[4*j+2] = fmaf(ps, v[j].z, t);
            t = cx[4*j+3] * resc; cx[4*j+3] = fmaf(ps, v[j].w, t);
        }
    }

    // Cross-warp tree merge of (m, s, c) online-softmax partials.
#pragma unroll
    for (int half = NW / 2; half >= 1; half >>= 1) {
        __syncthreads();
        if (w >= half && w < 2 * half) {
            const int slot = w - half;
#pragma unroll
            for (int j = 0; j < 8; j++)
                red_c[slot * (HH / 4) + j * 32 + l] =
                    make_float4(cx[4*j], cx[4*j+1], cx[4*j+2], cx[4*j+3]);
            if (l == 0) { red_m[slot] = mw; red_s[slot] = sw; }
        }
        __syncthreads();
        if (w < half) {
            const float mo = red_m[w], so = red_s[w];
            const float M  = fmaxf(mw, mo);
            const float ea = __expf(mw - M);
            const float eb = __expf(mo - M);
#pragma unroll
            for (int j = 0; j < 8; j++) {
                float4 o = red_c[w * (HH / 4) + j * 32 + l];
                cx[4*j+0] = cx[4*j+0] * ea + o.x * eb;
                cx[4*j+1] = cx[4*j+1] * ea + o.y * eb;
                cx[4*j+2] = cx[4*j+2] * ea + o.z * eb;
                cx[4*j+3] = cx[4*j+3] * ea + o.w * eb;
            }
            sw = sw * ea + so * eb;
            mw = M;
        }
    }

    if (w == 0) {
        float4* cp = reinterpret_cast<float4*>(g_cpart)
                   + (size_t)(b * RANGES + r) * (HH / 4);
#pragma unroll
        for (int j = 0; j < 8; j++)
            cp[j * 32 + l] = make_float4(cx[4*j], cx[4*j+1], cx[4*j+2], cx[4*j+3]);
        if (l == 0) {
            g_mpart[b * RANGES + r] = mw;
            g_spart[b * RANGES + r] = sw;
        }
    }
    __syncthreads();
    __threadfence();                 // publish this block's partials

    if (tid == 0) s_ticket = atomicAdd(&g_cnt[b], 1);
    __syncthreads();

    // ---- last block of this batch: combine the 64 partials -> out[b] ----
    if (s_ticket == RANGES - 1) {
        __threadfence();             // acquire others' partials

        if (tid < 32) {              // warp 0: merge weights (2 ranges/lane)
            float m0 = g_mpart[b * RANGES + tid];
            float m1 = g_mpart[b * RANGES + tid + 32];
            float s0 = g_spart[b * RANGES + tid];
            float s1 = g_spart[b * RANGES + tid + 32];
            float M = fmaxf(m0, m1);
#pragma unroll
            for (int off = 16; off; off >>= 1)
                M = fmaxf(M, __shfl_xor_sync(0xFFFFFFFFu, M, off));
            const float wg0 = __expf(m0 - M);
            const float wg1 = __expf(m1 - M);
            float D = s0 * wg0 + s1 * wg1;
#pragma unroll
            for (int off = 16; off; off >>= 1)
                D += __shfl_xor_sync(0xFFFFFFFFu, D, off);
            s_wgt[tid]      = wg0;
            s_wgt[tid + 32] = wg1;
            if (tid == 0) s_invD = 1.f / D;
        }
        __syncthreads();

        const float4* cp = reinterpret_cast<const float4*>(g_cpart)
                         + (size_t)b * RANGES * (HH / 4) + tid;
        float4 acc = make_float4(0.f, 0.f, 0.f, 0.f);
#pragma unroll 8
        for (int rr = 0; rr < RANGES; rr++) {
            const float wg = s_wgt[rr];
            float4 c4 = cp[(size_t)rr * (HH / 4)];
            acc.x = fmaf(wg, c4.x, acc.x);
            acc.y = fmaf(wg, c4.y, acc.y);
            acc.z = fmaf(wg, c4.z, acc.z);
            acc.w = fmaf(wg, c4.w, acc.w);
        }
        const float inv = s_invD;
        reinterpret_cast<float4*>(out)[b * (HH / 4) + tid] =
            make_float4(acc.x * inv, acc.y * inv, acc.z * inv, acc.w * inv);

        // Re-arm for the next graph replay: zero q[b], reset the counter.
        reinterpret_cast<float4*>(g_q)[b * (HH / 4) + tid] =
            make_float4(0.f, 0.f, 0.f, 0.f);
        __syncthreads();
        if (tid == 0) {
            __threadfence();
            g_cnt[b] = 0;
        }
    }
}

// ---------------------------------------------------------------------
extern "C" void kernel_launch(void* const* d_in, const int* in_sizes, int n_in,
                              void* d_out, int out_size) {
    const float* value = (const float*)d_in[0];  // [B,T,H]
    const float* last  = (const float*)d_in[1];  // [B,H]
    const float* W     = (const float*)d_in[2];  // [H,H]
    // d_in[3] = bias: constant per-batch shift in scores, cancels in softmax.
    float* out = (float*)d_out;                  // [B,1,H]
    (void)in_sizes; (void)n_in; (void)out_size;

    dim3 gq(HH / 128, OCH);
    k_query<<<gq, 128>>>(W, last);

    dim3 gf(RANGES, BB);
    k_fused<<<gf, 256>>>(value, out);
}

// round 13
// speedup vs baseline: 1.6659x; 1.6659x over previous
#include <cuda_runtime.h>
#include <cstdint>

// Shapes fixed: value [8,4096,1024], last [8,1024], W [1024,1024], b [1024].
#define BB 8
#define TT 4096
#define HH 1024

#define RANGES 32              // T-splits per batch (fused kernel grid.x)
#define TR (TT / RANGES)       // 128 timesteps per block
#define NW 8                   // warps per fused block (256 threads)
#define TROWS 8                // rows per async tile (one row per warp)
#define NT (TR / TROWS)        // 16 tiles
#define STAGES 3               // cp.async pipeline depth
#define TILE_F4 (TROWS * HH / 4)   // 2048 float4 = 32 KB per stage
#define DYN_SMEM (STAGES * TILE_F4 * 16)  // 96 KB

#define OCH 128                // o-splits for query
#define OSEG (HH / OCH)        // 8

// -------- scratch (__device__ globals; no allocation allowed) --------
// g_q: zero at load; re-zeroed by the fused kernel's combine epilogue each
// run, so the atomicAdd accumulation in k_query starts from 0 every replay.
__device__ __align__(16) float g_q[BB * HH];
__device__ __align__(16) float g_cpart[BB * RANGES * HH]; // 1 MB
__device__ float g_mpart[BB * RANGES];
__device__ float g_spart[BB * RANGES];
__device__ int   g_cnt[BB];   // per-batch ticket counters (reset by combiner)

// ---------------------------------------------------------------------
// Kernel 1: q[b,h] += sum_{o in chunk} W[o,h]*last[b,o], accumulated with
// atomicAdd (coalesced REDG). grid (HH/128, OCH) = 1024 blocks, block 128.
// ---------------------------------------------------------------------
__global__ void k_query(const float* __restrict__ W,
                        const float* __restrict__ last) {
    __shared__ float ls[BB * OSEG];   // 64 floats
    const int oc = blockIdx.y;
    const int h  = blockIdx.x * 128 + threadIdx.x;

    if (threadIdx.x < BB * OSEG) {
        int b = threadIdx.x / OSEG, o = threadIdx.x % OSEG;
        ls[threadIdx.x] = last[b * HH + oc * OSEG + o];
    }
    __syncthreads();

    float wv[OSEG];
#pragma unroll
    for (int o = 0; o < OSEG; o++)
        wv[o] = W[(size_t)(oc * OSEG + o) * HH + h];

    float acc[BB];
#pragma unroll
    for (int b = 0; b < BB; b++) acc[b] = 0.f;
#pragma unroll
    for (int o = 0; o < OSEG; o++) {
#pragma unroll
        for (int b = 0; b < BB; b++)
            acc[b] = fmaf(wv[o], ls[b * OSEG + o], acc[b]);
    }
#pragma unroll
    for (int b = 0; b < BB; b++)
        atomicAdd(&g_q[b * HH + h], acc[b]);
}

// ---------------------------------------------------------------------
// cp.async helpers
// ---------------------------------------------------------------------
__device__ __forceinline__ void cp_async16(void* smem_dst, const void* gmem_src) {
    unsigned dst = (unsigned)__cvta_generic_to_shared(smem_dst);
    asm volatile("cp.async.cg.shared.global [%0], [%1], 16;\n"
                 :: "r"(dst), "l"(gmem_src));
}
__device__ __forceinline__ void cp_commit() {
    asm volatile("cp.async.commit_group;\n" ::: "memory");
}
template <int N>
__device__ __forceinline__ void cp_wait() {
    asm volatile("cp.async.wait_group %0;\n" :: "n"(N) : "memory");
}

// ---------------------------------------------------------------------
// Kernel 2: fused score + online-softmax + context + last-block combine.
// cp.async 3-stage pipeline: 2 tiles (64 KB/CTA) of value permanently in
// flight to smem, independent of compute stalls -> DRAM stays fed while
// warps run the softmax dependency chain off LDS (29 cyc). R9 skeleton:
// grid (32, BB) = 256 blocks, 8 warps, warp w computes row w of each tile.
// red_c merge buffer aliases the stage memory (mainloop fully drained).
// Lane l, reg 4j+k maps to h = j*128 + l*4 + k.
// ---------------------------------------------------------------------
extern __shared__ float4 dyn[];   // STAGES * TILE_F4 float4s (96 KB)

__global__ __launch_bounds__(256, 2)
void k_fused(const float* __restrict__ value, float* __restrict__ out) {
    __shared__ float4 q_sm[HH / 4];               // 4 KB
    __shared__ float red_m[NW], red_s[NW];
    __shared__ float s_wgt[RANGES];
    __shared__ float s_invD;
    __shared__ int   s_ticket;

    const int b = blockIdx.y;
    const int r = blockIdx.x;
    const int tid = threadIdx.x;
    const int w = tid >> 5, l = tid & 31;

    const float4* vb = reinterpret_cast<const float4*>(value)
                     + ((size_t)b * TT + (size_t)r * TR) * (HH / 4);

    // Issue the first two tiles before anything else.
#pragma unroll
    for (int t = 0; t < 2; t++) {
        const float4* gsrc = vb + (size_t)t * TILE_F4 + tid;
        float4* sdst = dyn + t * TILE_F4 + tid;
#pragma unroll
        for (int k = 0; k < TILE_F4 / 256; k++)
            cp_async16(sdst + k * 256, gsrc + k * 256);
        cp_commit();
    }

    q_sm[tid] = reinterpret_cast<const float4*>(g_q)[b * (HH / 4) + tid];

    float cx[32];
#pragma unroll
    for (int i = 0; i < 32; i++) cx[i] = 0.f;
    float mw = -1e30f, sw = 0.f;

    for (int t = 0; t < NT; t++) {
        // Keep 2 tiles ahead in flight.
        if (t + 2 < NT) {
            const int s = (t + 2) % STAGES;
            const float4* gsrc = vb + (size_t)(t + 2) * TILE_F4 + tid;
            float4* sdst = dyn + s * TILE_F4 + tid;
#pragma unroll
            for (int k = 0; k < TILE_F4 / 256; k++)
                cp_async16(sdst + k * 256, gsrc + k * 256);
            cp_commit();
            cp_wait<2>();
        } else if (t + 1 < NT) {
            cp_wait<1>();
        } else {
            cp_wait<0>();
        }
        __syncthreads();   // tile t visible to all threads (also q_sm on t=0)

        // Warp w computes row w of tile t.
        const float4* row = dyn + (t % STAGES) * TILE_F4 + w * (HH / 4);
        float4 v[8];
#pragma unroll
        for (int j = 0; j < 8; j++) v[j] = row[j * 32 + l];

        float da = 0.f, db = 0.f;
#pragma unroll
        for (int j = 0; j < 8; j += 2) {
            float4 qa = q_sm[j * 32 + l];
            float4 qb = q_sm[(j + 1) * 32 + l];
            da = fmaf(v[j].x, qa.x, da);   db = fmaf(v[j+1].x, qb.x, db);
            da = fmaf(v[j].y, qa.y, da);   db = fmaf(v[j+1].y, qb.y, db);
            da = fmaf(v[j].z, qa.z, da);   db = fmaf(v[j+1].z, qb.z, db);
            da = fmaf(v[j].w, qa.w, da);   db = fmaf(v[j+1].w, qb.w, db);
        }
        float d = da + db;
#pragma unroll
        for (int off = 16; off; off >>= 1)
            d += __shfl_xor_sync(0xFFFFFFFFu, d, off);

        const float m_new = fmaxf(mw, d);
        const float resc  = __expf(mw - m_new);
        const float ps    = __expf(d - m_new);
        mw = m_new;
        sw = fmaf(sw, resc, ps);
#pragma unroll
        for (int j = 0; j < 8; j++) {
            float q0;
            q0 = cx[4*j+0] * resc; cx[4*j+0] = fmaf(ps, v[j].x, q0);
            q0 = cx[4*j+1] * resc; cx[4*j+1] = fmaf(ps, v[j].y, q0);
            q0 = cx[4*j+2] * resc; cx[4*j+2] = fmaf(ps, v[j].z, q0);
            q0 = cx[4*j+3] * resc; cx[4*j+3] = fmaf(ps, v[j].w, q0);
        }
        __syncthreads();   // all warps done reading stage before it's rewritten
    }

    // Cross-warp tree merge; red_c aliases the (drained) stage memory.
    float4* red_c = dyn;    // needs 4 * 256 float4 = 16 KB << 96 KB
#pragma unroll
    for (int half = NW / 2; half >= 1; half >>= 1) {
        __syncthreads();
        if (w >= half && w < 2 * half) {
            const int slot = w - half;
#pragma unroll
            for (int j = 0; j < 8; j++)
                red_c[slot * (HH / 4) + j * 32 + l] =
                    make_float4(cx[4*j], cx[4*j+1], cx[4*j+2], cx[4*j+3]);
            if (l == 0) { red_m[slot] = mw; red_s[slot] = sw; }
        }
        __syncthreads();
        if (w < half) {
            const float mo = red_m[w], so = red_s[w];
            const float M  = fmaxf(mw, mo);
            const float ea = __expf(mw - M);
            const float eb = __expf(mo - M);
#pragma unroll
            for (int j = 0; j < 8; j++) {
                float4 o = red_c[w * (HH / 4) + j * 32 + l];
                cx[4*j+0] = cx[4*j+0] * ea + o.x * eb;
                cx[4*j+1] = cx[4*j+1] * ea + o.y * eb;
                cx[4*j+2] = cx[4*j+2] * ea + o.z * eb;
                cx[4*j+3] = cx[4*j+3] * ea + o.w * eb;
            }
            sw = sw * ea + so * eb;
            mw = M;
        }
    }

    if (w == 0) {
        float4* cp = reinterpret_cast<float4*>(g_cpart)
                   + (size_t)(b * RANGES + r) * (HH / 4);
#pragma unroll
        for (int j = 0; j < 8; j++)
            cp[j * 32 + l] = make_float4(cx[4*j], cx[4*j+1], cx[4*j+2], cx[4*j+3]);
        if (l == 0) {
            g_mpart[b * RANGES + r] = mw;
            g_spart[b * RANGES + r] = sw;
        }
    }
    __syncthreads();
    __threadfence();                 // publish this block's partials

    if (tid == 0) s_ticket = atomicAdd(&g_cnt[b], 1);
    __syncthreads();

    // ---- last block of this batch: combine the 32 partials -> out[b] ----
    if (s_ticket == RANGES - 1) {
        __threadfence();             // acquire others' partials

        if (tid < 32) {              // warp 0: merge weights into smem
            float m = g_mpart[b * RANGES + tid];
            float s = g_spart[b * RANGES + tid];
            float M = m;
#pragma unroll
            for (int off = 16; off; off >>= 1)
                M = fmaxf(M, __shfl_xor_sync(0xFFFFFFFFu, M, off));
            const float wg = __expf(m - M);
            float D = s * wg;
#pragma unroll
            for (int off = 16; off; off >>= 1)
                D += __shfl_xor_sync(0xFFFFFFFFu, D, off);
            s_wgt[tid] = wg;
            if (tid == 0) s_invD = 1.f / D;
        }
        __syncthreads();

        const float4* cp = reinterpret_cast<const float4*>(g_cpart)
                         + (size_t)b * RANGES * (HH / 4) + tid;
        float4 acc = make_float4(0.f, 0.f, 0.f, 0.f);
#pragma unroll
        for (int rr = 0; rr < RANGES; rr++) {
            const float wg = s_wgt[rr];
            float4 c4 = cp[(size_t)rr * (HH / 4)];
            acc.x = fmaf(wg, c4.x, acc.x);
            acc.y = fmaf(wg, c4.y, acc.y);
            acc.z = fmaf(wg, c4.z, acc.z);
            acc.w = fmaf(wg, c4.w, acc.w);
        }
        const float inv = s_invD;
        reinterpret_cast<float4*>(out)[b * (HH / 4) + tid] =
            make_float4(acc.x * inv, acc.y * inv, acc.z * inv, acc.w * inv);

        // Re-arm for the next graph replay: zero q[b], reset the counter.
        reinterpret_cast<float4*>(g_q)[b * (HH / 4) + tid] =
            make_float4(0.f, 0.f, 0.f, 0.f);
        __syncthreads();
        if (tid == 0) {
            __threadfence();
            g_cnt[b] = 0;
        }
    }
}

// ---------------------------------------------------------------------
extern "C" void kernel_launch(void* const* d_in, const int* in_sizes, int n_in,
                              void* d_out, int out_size) {
    const float* value = (const float*)d_in[0];  // [B,T,H]
    const float* last  = (const float*)d_in[1];  // [B,H]
    const float* W     = (const float*)d_in[2];  // [H,H]
    // d_in[3] = bias: constant per-batch shift in scores, cancels in softmax.
    float* out = (float*)d_out;                  // [B,1,H]
    (void)in_sizes; (void)n_in; (void)out_size;

    static bool attr_set = false;   // host-side config, not device state
    if (!attr_set) {
        cudaFuncSetAttribute(k_fused,
                             cudaFuncAttributeMaxDynamicSharedMemorySize,
                             DYN_SMEM);
        attr_set = true;
    }

    dim3 gq(HH / 128, OCH);
    k_query<<<gq, 128>>>(W, last);

    dim3 gf(RANGES, BB);
    k_fused<<<gf, 256, DYN_SMEM>>>(value, out);
}

// round 14
// speedup vs baseline: 1.6784x; 1.0075x over previous
#include <cuda_runtime.h>
#include <cstdint>

// Shapes fixed: value [8,4096,1024], last [8,1024], W [1024,1024], b [1024].
#define BB 8
#define TT 4096
#define HH 1024

#define RANGES 32              // T-splits per batch (fused kernel grid.x)
#define TR (TT / RANGES)       // 128 timesteps per block
#define NW 8                   // warps per fused block (256 threads)
#define NITER (TR / NW)        // 16 rows per warp
#define SLOTS 3                // warp-private cp.async ring depth
#define ROW_F4 (HH / 4)        // 256 float4 per row (4 KB)
#define DYN_SMEM (NW * SLOTS * ROW_F4 * 16)   // 96 KB

#define OCH 128                // o-splits for query
#define OSEG (HH / OCH)        // 8

// -------- scratch (__device__ globals; no allocation allowed) --------
// g_q: zero at load; re-zeroed by the fused kernel's combine epilogue each
// run, so the atomicAdd accumulation in k_query starts from 0 every replay.
__device__ __align__(16) float g_q[BB * HH];
__device__ __align__(16) float g_cpart[BB * RANGES * HH]; // 1 MB
__device__ float g_mpart[BB * RANGES];
__device__ float g_spart[BB * RANGES];
__device__ int   g_cnt[BB];   // per-batch ticket counters (reset by combiner)

// ---------------------------------------------------------------------
// Kernel 1: q[b,h] += sum_{o in chunk} W[o,h]*last[b,o], accumulated with
// atomicAdd (coalesced REDG). grid (HH/128, OCH) = 1024 blocks, block 128.
// ---------------------------------------------------------------------
__global__ void k_query(const float* __restrict__ W,
                        const float* __restrict__ last) {
    __shared__ float ls[BB * OSEG];   // 64 floats
    const int oc = blockIdx.y;
    const int h  = blockIdx.x * 128 + threadIdx.x;

    if (threadIdx.x < BB * OSEG) {
        int b = threadIdx.x / OSEG, o = threadIdx.x % OSEG;
        ls[threadIdx.x] = last[b * HH + oc * OSEG + o];
    }
    __syncthreads();

    float wv[OSEG];
#pragma unroll
    for (int o = 0; o < OSEG; o++)
        wv[o] = W[(size_t)(oc * OSEG + o) * HH + h];

    float acc[BB];
#pragma unroll
    for (int b = 0; b < BB; b++) acc[b] = 0.f;
#pragma unroll
    for (int o = 0; o < OSEG; o++) {
#pragma unroll
        for (int b = 0; b < BB; b++)
            acc[b] = fmaf(wv[o], ls[b * OSEG + o], acc[b]);
    }
#pragma unroll
    for (int b = 0; b < BB; b++)
        atomicAdd(&g_q[b * HH + h], acc[b]);
}

// ---------------------------------------------------------------------
// cp.async helpers (per-thread groups -> per-warp pipelines need NO
// block synchronization).
// ---------------------------------------------------------------------
__device__ __forceinline__ void cp_async16(void* smem_dst, const void* gmem_src) {
    unsigned dst = (unsigned)__cvta_generic_to_shared(smem_dst);
    asm volatile("cp.async.cg.shared.global [%0], [%1], 16;\n"
                 :: "r"(dst), "l"(gmem_src));
}
__device__ __forceinline__ void cp_commit() {
    asm volatile("cp.async.commit_group;\n" ::: "memory");
}
template <int N>
__device__ __forceinline__ void cp_wait() {
    asm volatile("cp.async.wait_group %0;\n" :: "n"(N) : "memory");
}

// ---------------------------------------------------------------------
// Kernel 2: fused score + online-softmax + context + last-block combine.
// WARP-PRIVATE cp.async rings: warp w owns 3 x 4KB smem slots and keeps 2
// of ITS OWN rows in flight; commit/wait are per-thread so the mainloop
// has ZERO block barriers (R13's 32 __syncthreads were the regression).
// Lane l issues and consumes exactly slot elements j*32+l -> no cross-lane
// smem dependency. Grid (32, BB) = 256 blocks, 8 warps, 2 CTAs/SM.
// Lane l, reg 4j+k maps to h = j*128 + l*4 + k.
// ---------------------------------------------------------------------
extern __shared__ float4 dyn[];   // NW * SLOTS * ROW_F4 float4s (96 KB)

__global__ __launch_bounds__(256, 2)
void k_fused(const float* __restrict__ value, float* __restrict__ out) {
    __shared__ float4 q_sm[HH / 4];               // 4 KB
    __shared__ float red_m[NW], red_s[NW];
    __shared__ float s_wgt[RANGES];
    __shared__ float s_invD;
    __shared__ int   s_ticket;

    const int b = blockIdx.y;
    const int r = blockIdx.x;
    const int tid = threadIdx.x;
    const int w = tid >> 5, l = tid & 31;

    const float4* vb = reinterpret_cast<const float4*>(value)
                     + ((size_t)b * TT + (size_t)r * TR) * (HH / 4);
    float4* ring = dyn + w * (SLOTS * ROW_F4);    // this warp's 3 slots

    // Prologue: issue rows 0 and 1 of this warp (row t -> global t*NW+w).
#pragma unroll
    for (int t = 0; t < 2; t++) {
        const float4* gsrc = vb + (size_t)(t * NW + w) * ROW_F4;
        float4* sdst = ring + t * ROW_F4;
#pragma unroll
        for (int k = 0; k < 8; k++)
            cp_async16(sdst + k * 32 + l, gsrc + k * 32 + l);
        cp_commit();
    }

    q_sm[tid] = reinterpret_cast<const float4*>(g_q)[b * (HH / 4) + tid];
    __syncthreads();    // q_sm ready (only barrier before the merge phase)

    float cx[32];
#pragma unroll
    for (int i = 0; i < 32; i++) cx[i] = 0.f;
    float mw = -1e30f, sw = 0.f;

    for (int t = 0; t < NITER; t++) {
        if (t + 2 < NITER) {
            const float4* gsrc = vb + (size_t)((t + 2) * NW + w) * ROW_F4;
            float4* sdst = ring + ((t + 2) % SLOTS) * ROW_F4;
#pragma unroll
            for (int k = 0; k < 8; k++)
                cp_async16(sdst + k * 32 + l, gsrc + k * 32 + l);
            cp_commit();
            cp_wait<2>();          // row t complete (<=2 groups outstanding)
        } else if (t + 1 < NITER) {
            cp_wait<1>();
        } else {
            cp_wait<0>();
        }

        const float4* row = ring + (t % SLOTS) * ROW_F4;
        float4 v[8];
#pragma unroll
        for (int j = 0; j < 8; j++) v[j] = row[j * 32 + l];

        float da = 0.f, db = 0.f;
#pragma unroll
        for (int j = 0; j < 8; j += 2) {
            float4 qa = q_sm[j * 32 + l];
            float4 qb = q_sm[(j + 1) * 32 + l];
            da = fmaf(v[j].x, qa.x, da);   db = fmaf(v[j+1].x, qb.x, db);
            da = fmaf(v[j].y, qa.y, da);   db = fmaf(v[j+1].y, qb.y, db);
            da = fmaf(v[j].z, qa.z, da);   db = fmaf(v[j+1].z, qb.z, db);
            da = fmaf(v[j].w, qa.w, da);   db = fmaf(v[j+1].w, qb.w, db);
        }
        float d = da + db;
#pragma unroll
        for (int off = 16; off; off >>= 1)
            d += __shfl_xor_sync(0xFFFFFFFFu, d, off);

        const float m_new = fmaxf(mw, d);
        const float resc  = __expf(mw - m_new);
        const float ps    = __expf(d - m_new);
        mw = m_new;
        sw = fmaf(sw, resc, ps);
#pragma unroll
        for (int j = 0; j < 8; j++) {
            float t0;
            t0 = cx[4*j+0] * resc; cx[4*j+0] = fmaf(ps, v[j].x, t0);
            t0 = cx[4*j+1] * resc; cx[4*j+1] = fmaf(ps, v[j].y, t0);
            t0 = cx[4*j+2] * resc; cx[4*j+2] = fmaf(ps, v[j].z, t0);
            t0 = cx[4*j+3] * resc; cx[4*j+3] = fmaf(ps, v[j].w, t0);
        }
    }

    // Cross-warp tree merge; red_c aliases the (drained) ring memory.
    float4* red_c = dyn;    // needs 4 * 256 float4 = 16 KB << 96 KB
#pragma unroll
    for (int half = NW / 2; half >= 1; half >>= 1) {
        __syncthreads();
        if (w >= half && w < 2 * half) {
            const int slot = w - half;
#pragma unroll
            for (int j = 0; j < 8; j++)
                red_c[slot * (HH / 4) + j * 32 + l] =
                    make_float4(cx[4*j], cx[4*j+1], cx[4*j+2], cx[4*j+3]);
            if (l == 0) { red_m[slot] = mw; red_s[slot] = sw; }
        }
        __syncthreads();
        if (w < half) {
            const float mo = red_m[w], so = red_s[w];
            const float M  = fmaxf(mw, mo);
            const float ea = __expf(mw - M);
            const float eb = __expf(mo - M);
#pragma unroll
            for (int j = 0; j < 8; j++) {
                float4 o = red_c[w * (HH / 4) + j * 32 + l];
                cx[4*j+0] = cx[4*j+0] * ea + o.x * eb;
                cx[4*j+1] = cx[4*j+1] * ea + o.y * eb;
                cx[4*j+2] = cx[4*j+2] * ea + o.z * eb;
                cx[4*j+3] = cx[4*j+3] * ea + o.w * eb;
            }
            sw = sw * ea + so * eb;
            mw = M;
        }
    }

    if (w == 0) {
        float4* cp = reinterpret_cast<float4*>(g_cpart)
                   + (size_t)(b * RANGES + r) * (HH / 4);
#pragma unroll
        for (int j = 0; j < 8; j++)
            cp[j * 32 + l] = make_float4(cx[4*j], cx[4*j+1], cx[4*j+2], cx[4*j+3]);
        if (l == 0) {
            g_mpart[b * RANGES + r] = mw;
            g_spart[b * RANGES + r] = sw;
        }
    }
    __syncthreads();
    __threadfence();                 // publish this block's partials

    if (tid == 0) s_ticket = atomicAdd(&g_cnt[b], 1);
    __syncthreads();

    // ---- last block of this batch: combine the 32 partials -> out[b] ----
    if (s_ticket == RANGES - 1) {
        __threadfence();             // acquire others' partials

        if (tid < 32) {              // warp 0: merge weights into smem
            float m = g_mpart[b * RANGES + tid];
            float s = g_spart[b * RANGES + tid];
            float M = m;
#pragma unroll
            for (int off = 16; off; off >>= 1)
                M = fmaxf(M, __shfl_xor_sync(0xFFFFFFFFu, M, off));
            const float wg = __expf(m - M);
            float D = s * wg;
#pragma unroll
            for (int off = 16; off; off >>= 1)
                D += __shfl_xor_sync(0xFFFFFFFFu, D, off);
            s_wgt[tid] = wg;
            if (tid == 0) s_invD = 1.f / D;
        }
        __syncthreads();

        const float4* cp = reinterpret_cast<const float4*>(g_cpart)
                         + (size_t)b * RANGES * (HH / 4) + tid;
        float4 acc = make_float4(0.f, 0.f, 0.f, 0.f);
#pragma unroll
        for (int rr = 0; rr < RANGES; rr++) {
            const float wg = s_wgt[rr];
            float4 c4 = cp[(size_t)rr * (HH / 4)];
            acc.x = fmaf(wg, c4.x, acc.x);
            acc.y = fmaf(wg, c4.y, acc.y);
            acc.z = fmaf(wg, c4.z, acc.z);
            acc.w = fmaf(wg, c4.w, acc.w);
        }
        const float inv = s_invD;
        reinterpret_cast<float4*>(out)[b * (HH / 4) + tid] =
            make_float4(acc.x * inv, acc.y * inv, acc.z * inv, acc.w * inv);

        // Re-arm for the next graph replay: zero q[b], reset the counter.
        reinterpret_cast<float4*>(g_q)[b * (HH / 4) + tid] =
            make_float4(0.f, 0.f, 0.f, 0.f);
        __syncthreads();
        if (tid == 0) {
            __threadfence();
            g_cnt[b] = 0;
        }
    }
}

// ---------------------------------------------------------------------
extern "C" void kernel_launch(void* const* d_in, const int* in_sizes, int n_in,
                              void* d_out, int out_size) {
    const float* value = (const float*)d_in[0];  // [B,T,H]
    const float* last  = (const float*)d_in[1];  // [B,H]
    const float* W     = (const float*)d_in[2];  // [H,H]
    // d_in[3] = bias: constant per-batch shift in scores, cancels in softmax.
    float* out = (float*)d_out;                  // [B,1,H]
    (void)in_sizes; (void)n_in; (void)out_size;

    static bool attr_set = false;   // host-side config, not device state
    if (!attr_set) {
        cudaFuncSetAttribute(k_fused,
                             cudaFuncAttributeMaxDynamicSharedMemorySize,
                             DYN_SMEM);
        attr_set = true;
    }

    dim3 gq(HH / 128, OCH);
    k_query<<<gq, 128>>>(W, last);

    dim3 gf(RANGES, BB);
    k_fused<<<gf, 256, DYN_SMEM>>>(value, out);
}

// round 15
// speedup vs baseline: 2.0135x; 1.1996x over previous
#include <cuda_runtime.h>
#include <cstdint>

// Shapes fixed: value [8,4096,1024], last [8,1024], W [1024,1024], b [1024].
#define BB 8
#define TT 4096
#define HH 1024

#define RANGES 32              // T-splits per batch (fused kernel grid.x)
#define TR (TT / RANGES)       // 128 timesteps per block
#define NW 8                   // warps per fused block (256 threads)
#define RPW 2                  // rows per warp per iteration
#define NITER (TR / (NW * RPW))// 8 iterations

#define OCH 128                // o-splits for query
#define OSEG (HH / OCH)        // 8

// -------- scratch (__device__ globals; no allocation allowed) --------
// g_q: zero at load; re-zeroed by the fused kernel's combine epilogue each
// run, so the atomicAdd accumulation in k_query starts from 0 every replay.
__device__ __align__(16) float g_q[BB * HH];
__device__ __align__(16) float g_cpart[BB * RANGES * HH]; // 1 MB
__device__ float g_mpart[BB * RANGES];
__device__ float g_spart[BB * RANGES];
__device__ int   g_cnt[BB];   // per-batch ticket counters (reset by combiner)

// ---------------------------------------------------------------------
// Kernel 1: q[b,h] += sum_{o in chunk} W[o,h]*last[b,o], accumulated with
// atomicAdd (coalesced REDG). grid (HH/128, OCH) = 1024 blocks, block 128.
// ---------------------------------------------------------------------
__global__ void k_query(const float* __restrict__ W,
                        const float* __restrict__ last) {
    __shared__ float ls[BB * OSEG];   // 64 floats
    const int oc = blockIdx.y;
    const int h  = blockIdx.x * 128 + threadIdx.x;

    if (threadIdx.x < BB * OSEG) {
        int b = threadIdx.x / OSEG, o = threadIdx.x % OSEG;
        ls[threadIdx.x] = last[b * HH + oc * OSEG + o];
    }
    __syncthreads();

    float wv[OSEG];
#pragma unroll
    for (int o = 0; o < OSEG; o++)
        wv[o] = W[(size_t)(oc * OSEG + o) * HH + h];

    float acc[BB];
#pragma unroll
    for (int b = 0; b < BB; b++) acc[b] = 0.f;
#pragma unroll
    for (int o = 0; o < OSEG; o++) {
#pragma unroll
        for (int b = 0; b < BB; b++)
            acc[b] = fmaf(wv[o], ls[b * OSEG + o], acc[b]);
    }
#pragma unroll
    for (int b = 0; b < BB; b++)
        atomicAdd(&g_q[b * HH + h], acc[b]);
}

// ---------------------------------------------------------------------
// Kernel 2: fused score + LAZY-RESCALE online-softmax + context +
// last-block combine. R9's proven memory shape (RPW=2, MLP=16, 256
// blocks, 2 CTAs/SM) with the math chain shortened: cx is a PURE
// accumulator (cx += exp(d-offset)*v, 64 independent FMAs); the cx-wide
// rescale runs only on the warp-uniform rare event max(d0,d1) >
// offset+60 (first iteration triggers it from offset=-1e30, zeroing the
// zero cx -- harmless). exp args are in [-inf, 60] -> no overflow.
// (offset, sw, cx) is a valid (m, s, c) triple for the merge phases.
// Lane l, reg 4j+k maps to h = j*128 + l*4 + k.
// ---------------------------------------------------------------------
__global__ __launch_bounds__(256, 2)
void k_fused(const float* __restrict__ value, float* __restrict__ out) {
    __shared__ float4 q_sm[HH / 4];               // 4 KB
    __shared__ float4 red_c[(NW / 2) * (HH / 4)]; // 16 KB
    __shared__ float red_m[NW], red_s[NW];
    __shared__ float s_wgt[RANGES];
    __shared__ float s_invD;
    __shared__ int   s_ticket;

    const int b = blockIdx.y;
    const int r = blockIdx.x;
    const int tid = threadIdx.x;
    const int w = tid >> 5, l = tid & 31;

    q_sm[tid] = reinterpret_cast<const float4*>(g_q)[b * (HH / 4) + tid];
    __syncthreads();

    float cx[32];
#pragma unroll
    for (int i = 0; i < 32; i++) cx[i] = 0.f;
    float offset = -1e30f, sw = 0.f;

    const float4* vb = reinterpret_cast<const float4*>(value)
                     + ((size_t)b * TT + (size_t)r * TR) * (HH / 4);

    for (int it = 0; it < NITER; it++) {
        const int t0 = it * (NW * RPW) + w * RPW;
        const float4* p0 = vb + (size_t)t0 * (HH / 4) + l;
        const float4* p1 = p0 + (HH / 4);

        float4 v0[8], v1[8];
#pragma unroll
        for (int j = 0; j < 8; j++) v0[j] = p0[j * 32];
#pragma unroll
        for (int j = 0; j < 8; j++) v1[j] = p1[j * 32];

        float d0 = 0.f, d1 = 0.f;
#pragma unroll
        for (int j = 0; j < 8; j++) {
            float4 q = q_sm[j * 32 + l];
            d0 = fmaf(v0[j].x, q.x, d0); d0 = fmaf(v0[j].y, q.y, d0);
            d0 = fmaf(v0[j].z, q.z, d0); d0 = fmaf(v0[j].w, q.w, d0);
            d1 = fmaf(v1[j].x, q.x, d1); d1 = fmaf(v1[j].y, q.y, d1);
            d1 = fmaf(v1[j].z, q.z, d1); d1 = fmaf(v1[j].w, q.w, d1);
        }
#pragma unroll
        for (int off = 16; off; off >>= 1) {
            d0 += __shfl_xor_sync(0xFFFFFFFFu, d0, off);
            d1 += __shfl_xor_sync(0xFFFFFFFFu, d1, off);
        }

        // Lazy rescale: only when a score threatens exp overflow headroom.
        const float dmax = fmaxf(d0, d1);
        if (dmax > offset + 60.f) {          // warp-uniform, rare
            const float f = __expf(offset - dmax);
            offset = dmax;
            sw *= f;
#pragma unroll
            for (int i = 0; i < 32; i++) cx[i] *= f;
        }
        const float p0s = __expf(d0 - offset);
        const float p1s = __expf(d1 - offset);
        sw += p0s + p1s;
        // Pure accumulation: 64 independent FMAs, no serial cx chain.
#pragma unroll
        for (int j = 0; j < 8; j++) {
            cx[4*j+0] = fmaf(p0s, v0[j].x, cx[4*j+0]);
            cx[4*j+1] = fmaf(p0s, v0[j].y, cx[4*j+1]);
            cx[4*j+2] = fmaf(p0s, v0[j].z, cx[4*j+2]);
            cx[4*j+3] = fmaf(p0s, v0[j].w, cx[4*j+3]);
        }
#pragma unroll
        for (int j = 0; j < 8; j++) {
            cx[4*j+0] = fmaf(p1s, v1[j].x, cx[4*j+0]);
            cx[4*j+1] = fmaf(p1s, v1[j].y, cx[4*j+1]);
            cx[4*j+2] = fmaf(p1s, v1[j].z, cx[4*j+2]);
            cx[4*j+3] = fmaf(p1s, v1[j].w, cx[4*j+3]);
        }
    }
    float mw = offset;

    // Cross-warp tree merge of (m, s, c) online-softmax partials.
#pragma unroll
    for (int half = NW / 2; half >= 1; half >>= 1) {
        __syncthreads();
        if (w >= half && w < 2 * half) {
            const int slot = w - half;
#pragma unroll
            for (int j = 0; j < 8; j++)
                red_c[slot * (HH / 4) + j * 32 + l] =
                    make_float4(cx[4*j], cx[4*j+1], cx[4*j+2], cx[4*j+3]);
            if (l == 0) { red_m[slot] = mw; red_s[slot] = sw; }
        }
        __syncthreads();
        if (w < half) {
            const float mo = red_m[w], so = red_s[w];
            const float M  = fmaxf(mw, mo);
            const float ea = __expf(mw - M);
            const float eb = __expf(mo - M);
#pragma unroll
            for (int j = 0; j < 8; j++) {
                float4 o = red_c[w * (HH / 4) + j * 32 + l];
                cx[4*j+0] = cx[4*j+0] * ea + o.x * eb;
                cx[4*j+1] = cx[4*j+1] * ea + o.y * eb;
                cx[4*j+2] = cx[4*j+2] * ea + o.z * eb;
                cx[4*j+3] = cx[4*j+3] * ea + o.w * eb;
            }
            sw = sw * ea + so * eb;
            mw = M;
        }
    }

    if (w == 0) {
        float4* cp = reinterpret_cast<float4*>(g_cpart)
                   + (size_t)(b * RANGES + r) * (HH / 4);
#pragma unroll
        for (int j = 0; j < 8; j++)
            cp[j * 32 + l] = make_float4(cx[4*j], cx[4*j+1], cx[4*j+2], cx[4*j+3]);
        if (l == 0) {
            g_mpart[b * RANGES + r] = mw;
            g_spart[b * RANGES + r] = sw;
        }
    }
    __syncthreads();
    __threadfence();                 // publish this block's partials

    if (tid == 0) s_ticket = atomicAdd(&g_cnt[b], 1);
    __syncthreads();

    // ---- last block of this batch: combine the 32 partials -> out[b] ----
    if (s_ticket == RANGES - 1) {
        __threadfence();             // acquire others' partials

        if (tid < 32) {              // warp 0: merge weights into smem
            float m = g_mpart[b * RANGES + tid];
            float s = g_spart[b * RANGES + tid];
            float M = m;
#pragma unroll
            for (int off = 16; off; off >>= 1)
                M = fmaxf(M, __shfl_xor_sync(0xFFFFFFFFu, M, off));
            const float wg = __expf(m - M);
            float D = s * wg;
#pragma unroll
            for (int off = 16; off; off >>= 1)
                D += __shfl_xor_sync(0xFFFFFFFFu, D, off);
            s_wgt[tid] = wg;
            if (tid == 0) s_invD = 1.f / D;
        }
        __syncthreads();

        const float4* cp = reinterpret_cast<const float4*>(g_cpart)
                         + (size_t)b * RANGES * (HH / 4) + tid;
        float4 acc = make_float4(0.f, 0.f, 0.f, 0.f);
#pragma unroll
        for (int rr = 0; rr < RANGES; rr++) {
            const float wg = s_wgt[rr];
            float4 c4 = cp[(size_t)rr * (HH / 4)];
            acc.x = fmaf(wg, c4.x, acc.x);
            acc.y = fmaf(wg, c4.y, acc.y);
            acc.z = fmaf(wg, c4.z, acc.z);
            acc.w = fmaf(wg, c4.w, acc.w);
        }
        const float inv = s_invD;
        reinterpret_cast<float4*>(out)[b * (HH / 4) + tid] =
            make_float4(acc.x * inv, acc.y * inv, acc.z * inv, acc.w * inv);

        // Re-arm for the next graph replay: zero q[b], reset the counter.
        reinterpret_cast<float4*>(g_q)[b * (HH / 4) + tid] =
            make_float4(0.f, 0.f, 0.f, 0.f);
        __syncthreads();
        if (tid == 0) {
            __threadfence();
            g_cnt[b] = 0;
        }
    }
}

// ---------------------------------------------------------------------
extern "C" void kernel_launch(void* const* d_in, const int* in_sizes, int n_in,
                              void* d_out, int out_size) {
    const float* value = (const float*)d_in[0];  // [B,T,H]
    const float* last  = (const float*)d_in[1];  // [B,H]
    const float* W     = (const float*)d_in[2];  // [H,H]
    // d_in[3] = bias: constant per-batch shift in scores, cancels in softmax.
    float* out = (float*)d_out;                  // [B,1,H]
    (void)in_sizes; (void)n_in; (void)out_size;

    dim3 gq(HH / 128, OCH);
    k_query<<<gq, 128>>>(W, last);

    dim3 gf(RANGES, BB);
    k_fused<<<gf, 256>>>(value, out);
}